// round 6
// baseline (speedup 1.0000x reference)
#include <cuda_runtime.h>
#include <cstdint>

#define VOCAB 100000
#define EMBED 128

// 51.2 MB transposed weight scratch: Wt[v][e] = W[e][v]
__device__ __align__(16) float g_Wt[(size_t)VOCAB * EMBED];
// index-dtype flag: 1 = int64 indices, 0 = int32 indices
__device__ int g_is64;

// ---------------------------------------------------------------------------
// Detect index dtype. Values are in [0, VOCAB) < 2^31, so if the buffer is
// int64 the odd 32-bit words are all zero. For int32 data the odd words are
// random indices; P(8 consecutive odd words all zero) ~ 1e-40.
// ---------------------------------------------------------------------------
__global__ void detect_kernel(const unsigned int* __restrict__ xw) {
    if (threadIdx.x == 0) {
        int is64 = 1;
#pragma unroll
        for (int i = 0; i < 8; i++)
            if (xw[2 * i + 1] != 0u) is64 = 0;
        g_is64 = is64;
    }
}

// ---------------------------------------------------------------------------
// Transpose W [EMBED=128, VOCAB] -> g_Wt [VOCAB, EMBED].
// One block handles a 128(e) x 32(v) tile. 256 threads.
// Load: warp reads 32 consecutive v for fixed e  -> 128B coalesced.
// smem pad 129: store s[j*129+e] with lanes varying j -> banks (j+e)%32, no conflict.
// Store: consecutive tid -> consecutive e for fixed v -> 128B coalesced,
//        smem read s[vr*129+e] lanes consecutive e -> conflict-free.
// ---------------------------------------------------------------------------
__global__ void transpose_kernel(const float* __restrict__ W) {
    __shared__ float s[32 * 129];
    const int v0 = blockIdx.x * 32;
    const int tid = threadIdx.x;       // 0..255
    const int j = tid & 31;            // v within tile
    const int eb = tid >> 5;           // 0..7

#pragma unroll
    for (int k = 0; k < 16; k++) {
        int e = eb + k * 8;            // 0..127
        s[j * 129 + e] = W[(size_t)e * VOCAB + (v0 + j)];
    }
    __syncthreads();

#pragma unroll
    for (int m = 0; m < 16; m++) {
        int idx = m * 256 + tid;       // 0..4095
        int vr = idx >> 7;             // 0..31
        int e  = idx & 127;            // 0..127
        g_Wt[(size_t)(v0 + vr) * EMBED + e] = s[vr * 129 + e];
    }
}

// ---------------------------------------------------------------------------
// Gather: one warp per token. Each lane moves one float4 (lane*4..lane*4+3 of
// the 128-wide embedding). Reads are 512B contiguous per warp (L2-resident
// Wt), writes are 512B contiguous, streamed with __stcs to avoid evicting Wt
// from L2.
// ---------------------------------------------------------------------------
__global__ void gather_kernel(const void* __restrict__ xraw,
                              const float* __restrict__ bias,
                              float* __restrict__ out,
                              int ntok) {
    const int gwarp = (int)((blockIdx.x * (unsigned)blockDim.x + threadIdx.x) >> 5);
    const int lane = threadIdx.x & 31;
    if (gwarp >= ntok) return;

    long long idx;
    if (g_is64) idx = ((const long long*)xraw)[gwarp];
    else        idx = (long long)((const int*)xraw)[gwarp];

    const float4* wrow = (const float4*)(g_Wt + (size_t)idx * EMBED);
    float4 w = __ldg(wrow + lane);
    float4 bb = __ldg((const float4*)bias + lane);
    float4 r = make_float4(w.x + bb.x, w.y + bb.y, w.z + bb.z, w.w + bb.w);
    __stcs(((float4*)out) + (size_t)gwarp * (EMBED / 4) + lane, r);
}

// ---------------------------------------------------------------------------
// Inputs (metadata order): d_in[0] = x [4096*200] int32/int64,
//                          d_in[1] = W [128*100000] f32,
//                          d_in[2] = b [128] f32.
// Output: [4096*200*128] f32.
// ---------------------------------------------------------------------------
extern "C" void kernel_launch(void* const* d_in, const int* in_sizes, int n_in,
                              void* d_out, int out_size) {
    const void* x = d_in[0];
    const float* W = (const float*)d_in[1];
    const float* b = (const float*)d_in[2];
    float* out = (float*)d_out;
    const int ntok = in_sizes[0];  // 819200 tokens (element count, dtype-independent)

    detect_kernel<<<1, 32>>>((const unsigned int*)x);

    // VOCAB = 100000 = 3125 tiles of 32 columns
    transpose_kernel<<<VOCAB / 32, 256>>>(W);

    // 8 warps per 256-thread block -> 1 token per warp
    const int warps_per_block = 256 / 32;
    const int nblk = (ntok + warps_per_block - 1) / warps_per_block;
    gather_kernel<<<nblk, 256>>>(x, b, out, ntok);
}

// round 11
// speedup vs baseline: 1.3200x; 1.3200x over previous
#include <cuda_runtime.h>
#include <cstdint>

#define VOCAB 100000
#define EMBED 128

// 51.2 MB transposed (+bias-fused) weight scratch: g_Wt[v][e] = W[e][v] + b[e]
// 32B alignment required for v8.f32 accesses.
__device__ __align__(32) float g_Wt[(size_t)VOCAB * EMBED];
// index-dtype flag: 1 = int64 indices, 0 = int32 indices
__device__ int g_is64;

// ---- 256-bit L2 eviction-policy accessors (sm_103 requires .v8.f32) -------
__device__ __forceinline__ void ldg8_evict_last(const float* p, float* v) {
    asm volatile(
        "ld.global.nc.L2::evict_last.v8.f32 {%0,%1,%2,%3,%4,%5,%6,%7}, [%8];"
        : "=f"(v[0]), "=f"(v[1]), "=f"(v[2]), "=f"(v[3]),
          "=f"(v[4]), "=f"(v[5]), "=f"(v[6]), "=f"(v[7])
        : "l"(p));
}
__device__ __forceinline__ void stg8_evict_first(float* p, const float* v) {
    asm volatile(
        "st.global.L2::evict_first.v8.f32 [%0], {%1,%2,%3,%4,%5,%6,%7,%8};"
        :: "l"(p),
           "f"(v[0]), "f"(v[1]), "f"(v[2]), "f"(v[3]),
           "f"(v[4]), "f"(v[5]), "f"(v[6]), "f"(v[7])
        : "memory");
}

// ---------------------------------------------------------------------------
// Transpose W [EMBED=128, VOCAB] -> g_Wt [VOCAB, EMBED], fusing the bias add
// and the index-dtype detection (block 0, thread 0).
//
// One block handles a 128(e) x 32(v) tile. 256 threads.
// Load:  warp reads 32 consecutive v for fixed e  -> 128B coalesced.
// smem pad 129: s[j*129+e], lanes vary j -> banks (j+e)%32, conflict-free.
// Store: consecutive tid -> consecutive e for fixed v -> 128B coalesced,
//        smem read s[vr*129+e] lanes consecutive e -> conflict-free.
// Stores are default-policy; the gather's evict_last READS pin Wt in L2.
// ---------------------------------------------------------------------------
__global__ __launch_bounds__(256) void transpose_kernel(
    const float* __restrict__ W,
    const float* __restrict__ bias,
    const unsigned int* __restrict__ xw)
{
    __shared__ float s[32 * 129];
    __shared__ float sb[EMBED];

    const int v0 = blockIdx.x * 32;
    const int tid = threadIdx.x;       // 0..255
    const int j = tid & 31;            // v within tile
    const int eb = tid >> 5;           // 0..7

    // dtype detection: indices < 2^31, so int64 buffers have zero odd words.
    // P(false positive on int32 data) ~ (2^-32)^8.
    if (blockIdx.x == 0 && tid == 0) {
        int is64 = 1;
#pragma unroll
        for (int i = 0; i < 8; i++)
            if (xw[2 * i + 1] != 0u) is64 = 0;
        g_is64 = is64;
    }

    if (tid < EMBED) sb[tid] = bias[tid];

#pragma unroll
    for (int k = 0; k < 16; k++) {
        int e = eb + k * 8;            // 0..127
        s[j * 129 + e] = W[(size_t)e * VOCAB + (v0 + j)];
    }
    __syncthreads();

#pragma unroll
    for (int m = 0; m < 16; m++) {
        int idx = m * 256 + tid;       // 0..4095
        int vr = idx >> 7;             // 0..31
        int e  = idx & 127;            // 0..127
        g_Wt[(size_t)(v0 + vr) * EMBED + e] = s[vr * 129 + e] + sb[e];
    }
}

// ---------------------------------------------------------------------------
// Gather: 2 tokens per warp. Lane l serves token (warp*2 + l/16), segment
// l%16; each lane moves one 32B chunk (8 floats) of the 512B row.
// Reads:  v8 + L2::evict_last  -> Wt (51.2MB) stays pinned in L2 (126MB).
// Writes: v8 + L2::evict_first -> 419MB output stream recycles a small
//         L2 slice instead of displacing Wt.
// ---------------------------------------------------------------------------
__global__ __launch_bounds__(256) void gather_kernel(
    const void* __restrict__ xraw,
    float* __restrict__ out,
    int ntok)
{
    const int tid = (int)(blockIdx.x * 256u + threadIdx.x);
    const int tok = tid >> 4;          // 16 lanes per token
    const int seg = tid & 15;          // which 32B chunk of the row
    if (tok >= ntok) return;

    long long idx;
    if (g_is64) idx = ((const long long*)xraw)[tok];
    else        idx = (long long)((const int*)xraw)[tok];

    float v[8];
    ldg8_evict_last(g_Wt + (size_t)idx * EMBED + seg * 8, v);
    stg8_evict_first(out + (size_t)tok * EMBED + seg * 8, v);
}

// ---------------------------------------------------------------------------
// Inputs (metadata order): d_in[0] = x [4096*200] int32/int64,
//                          d_in[1] = W [128*100000] f32,
//                          d_in[2] = b [128] f32.
// Output: [4096*200*128] f32.
// ---------------------------------------------------------------------------
extern "C" void kernel_launch(void* const* d_in, const int* in_sizes, int n_in,
                              void* d_out, int out_size) {
    const void* x = d_in[0];
    const float* W = (const float*)d_in[1];
    const float* b = (const float*)d_in[2];
    float* out = (float*)d_out;
    const int ntok = in_sizes[0];  // 819200 tokens (element count, dtype-independent)

    // VOCAB = 100000 = 3125 tiles of 32 columns
    transpose_kernel<<<VOCAB / 32, 256>>>(W, b, (const unsigned int*)x);

    // 256 threads = 16 tokens per block
    const int tok_per_block = 16;
    const int nblk = (ntok + tok_per_block - 1) / tok_per_block;
    gather_kernel<<<nblk, 256>>>(x, out, ntok);
}

// round 12
// speedup vs baseline: 1.4508x; 1.0991x over previous
#include <cuda_runtime.h>
#include <cstdint>

#define VOCAB 100000
#define EMBED 128

// 51.2 MB transposed (+bias-fused) weight scratch: g_Wt[v][e] = W[e][v] + b[e]
// 32B alignment required for v8.f32 accesses.
__device__ __align__(32) float g_Wt[(size_t)VOCAB * EMBED];
// index-dtype flag: 1 = int64 indices, 0 = int32 indices
__device__ int g_is64;

// ---- 256-bit L2 eviction-policy accessors (sm_103 requires .v8.f32) -------
__device__ __forceinline__ void ldg8_evict_last(const float* p, float* v) {
    asm volatile(
        "ld.global.nc.L2::evict_last.v8.f32 {%0,%1,%2,%3,%4,%5,%6,%7}, [%8];"
        : "=f"(v[0]), "=f"(v[1]), "=f"(v[2]), "=f"(v[3]),
          "=f"(v[4]), "=f"(v[5]), "=f"(v[6]), "=f"(v[7])
        : "l"(p));
}
__device__ __forceinline__ void stg8_evict_first(float* p, const float* v) {
    asm volatile(
        "st.global.L2::evict_first.v8.f32 [%0], {%1,%2,%3,%4,%5,%6,%7,%8};"
        :: "l"(p),
           "f"(v[0]), "f"(v[1]), "f"(v[2]), "f"(v[3]),
           "f"(v[4]), "f"(v[5]), "f"(v[6]), "f"(v[7])
        : "memory");
}

// ---------------------------------------------------------------------------
// Transpose W [EMBED=128, VOCAB] -> g_Wt [VOCAB, EMBED], fusing the bias add
// and the index-dtype detection (block 0, thread 0).
//
// One block handles a 128(e) x 32(v) tile. 256 threads.
// Load:  warp reads 32 consecutive v for fixed e  -> 128B coalesced.
// smem pad 129: s[j*129+e], lanes vary j -> banks (j+e)%32, conflict-free.
// Store: consecutive tid -> consecutive e for fixed v -> 128B coalesced,
//        smem read s[vr*129+e] lanes consecutive e -> conflict-free.
// Measured ~14us ≈ its 102MB bandwidth floor — unchanged this round.
// ---------------------------------------------------------------------------
__global__ __launch_bounds__(256) void transpose_kernel(
    const float* __restrict__ W,
    const float* __restrict__ bias,
    const unsigned int* __restrict__ xw)
{
    __shared__ float s[32 * 129];
    __shared__ float sb[EMBED];

    const int v0 = blockIdx.x * 32;
    const int tid = threadIdx.x;       // 0..255
    const int j = tid & 31;            // v within tile
    const int eb = tid >> 5;           // 0..7

    // dtype detection: indices < 2^31, so int64 buffers have zero odd words.
    // P(false positive on int32 data) ~ (2^-32)^8.
    if (blockIdx.x == 0 && tid == 0) {
        int is64 = 1;
#pragma unroll
        for (int i = 0; i < 8; i++)
            if (xw[2 * i + 1] != 0u) is64 = 0;
        g_is64 = is64;
    }

    if (tid < EMBED) sb[tid] = bias[tid];

#pragma unroll
    for (int k = 0; k < 16; k++) {
        int e = eb + k * 8;            // 0..127
        s[j * 129 + e] = W[(size_t)e * VOCAB + (v0 + j)];
    }
    __syncthreads();

#pragma unroll
    for (int m = 0; m < 16; m++) {
        int idx = m * 256 + tid;       // 0..4095
        int vr = idx >> 7;             // 0..31
        int e  = idx & 127;            // 0..127
        g_Wt[(size_t)(v0 + vr) * EMBED + e] = s[vr * 129 + e] + sb[e];
    }
}

// ---------------------------------------------------------------------------
// Gather, MLP=2: each 256-thread block serves 32 tokens; every thread handles
// TWO tokens (tokA = base + tid/16, tokB = tokA + 16), issuing both
// independent v8 loads before either store. This doubles outstanding
// requests per thread — previous version (MLP=1) left DRAM at 68.6% with
// issue at 13%: latency-limited, not traffic-limited.
//
// Reads:  v8 + L2::evict_last  -> Wt (51.2MB) stays pinned in L2 (126MB).
// Writes: v8 + L2::evict_first -> 419MB output stream recycles a small
//         L2 slice instead of displacing Wt. Warp stores remain 1024B
//         contiguous per store instruction.
// ---------------------------------------------------------------------------
__global__ __launch_bounds__(256, 8) void gather_kernel(
    const void* __restrict__ xraw,
    float* __restrict__ out,
    int ntok)
{
    const int tid = threadIdx.x;
    const int seg = tid & 15;                          // 32B chunk of the row
    const int tokA = blockIdx.x * 32 + (tid >> 4);     // tokens 0..15 of block
    const int tokB = tokA + 16;                        // tokens 16..31 of block

    long long idxA, idxB;
    if (g_is64) {
        const long long* xp = (const long long*)xraw;
        idxA = (tokA < ntok) ? xp[tokA] : 0;
        idxB = (tokB < ntok) ? xp[tokB] : 0;
    } else {
        const int* xp = (const int*)xraw;
        idxA = (tokA < ntok) ? (long long)xp[tokA] : 0;
        idxB = (tokB < ntok) ? (long long)xp[tokB] : 0;
    }

    float a[8], bv[8];
    // two independent loads in flight before any store
    ldg8_evict_last(g_Wt + (size_t)idxA * EMBED + seg * 8, a);
    ldg8_evict_last(g_Wt + (size_t)idxB * EMBED + seg * 8, bv);

    if (tokA < ntok) stg8_evict_first(out + (size_t)tokA * EMBED + seg * 8, a);
    if (tokB < ntok) stg8_evict_first(out + (size_t)tokB * EMBED + seg * 8, bv);
}

// ---------------------------------------------------------------------------
// Inputs (metadata order): d_in[0] = x [4096*200] int32/int64,
//                          d_in[1] = W [128*100000] f32,
//                          d_in[2] = b [128] f32.
// Output: [4096*200*128] f32.
// ---------------------------------------------------------------------------
extern "C" void kernel_launch(void* const* d_in, const int* in_sizes, int n_in,
                              void* d_out, int out_size) {
    const void* x = d_in[0];
    const float* W = (const float*)d_in[1];
    const float* b = (const float*)d_in[2];
    float* out = (float*)d_out;
    const int ntok = in_sizes[0];  // 819200 tokens (element count, dtype-independent)

    // VOCAB = 100000 = 3125 tiles of 32 columns
    transpose_kernel<<<VOCAB / 32, 256>>>(W, b, (const unsigned int*)x);

    // 32 tokens per 256-thread block (2 tokens per thread)
    const int tok_per_block = 32;
    const int nblk = (ntok + tok_per_block - 1) / tok_per_block;
    gather_kernel<<<nblk, 256>>>(x, out, ntok);
}